// round 14
// baseline (speedup 1.0000x reference)
#include <cuda_runtime.h>
#include <math.h>

#define VOCAB     50257
#define NROWS     2048
#define TOPK      50
#define MASK_ID   50256
#define TOPP      0.9f
#define NCAND     2048
#define THREADS   256
#define RPC       256             // rows per CTA (1 per thread)
#define GRID      (NROWS / RPC)   // 8 CTAs, 2048 threads total

// Order-preserving uint key for float comparison (ascending).
__device__ __forceinline__ unsigned ordkey(float f) {
    unsigned u = __float_as_uint(f);
    return (u & 0x80000000u) ? ~u : (u | 0x80000000u);
}

// Threefry-2x32 with key (0, 42)  [jax.random.key(42)]
__device__ __forceinline__ void threefry42(unsigned x0, unsigned x1,
                                           unsigned& o0, unsigned& o1) {
    const unsigned ks0 = 0u;
    const unsigned ks1 = 42u;
    const unsigned ks2 = 0x1BD11BF0u;  // 0x1BD11BDA ^ 0 ^ 42
    x0 += ks0; x1 += ks1;
#define TF_RND(r) { x0 += x1; x1 = (x1 << (r)) | (x1 >> (32 - (r))); x1 ^= x0; }
    TF_RND(13) TF_RND(15) TF_RND(26) TF_RND(6)   x0 += ks1; x1 += ks2 + 1u;
    TF_RND(17) TF_RND(29) TF_RND(16) TF_RND(24)  x0 += ks2; x1 += ks0 + 2u;
    TF_RND(13) TF_RND(15) TF_RND(26) TF_RND(6)   x0 += ks0; x1 += ks1 + 3u;
    TF_RND(17) TF_RND(29) TF_RND(16) TF_RND(24)  x0 += ks1; x1 += ks2 + 4u;
    TF_RND(13) TF_RND(15) TF_RND(26) TF_RND(6)   x0 += ks2; x1 += ks0 + 5u;
#undef TF_RND
    o0 = x0; o1 = x1;
}

// Gumbel noise for flat element index, matching jax.random.gumbel(key(42), (2,1024,50257)):
// threefry_random_bits: counts = iota(N), split halves; bits = concat(out0, out1).
__device__ __forceinline__ float gumbel_at(long long flat) {
    const long long total = (long long)NROWS * VOCAB;   // even
    const long long half  = total / 2;
    unsigned bits, o0, o1;
    if (flat < half) {
        threefry42((unsigned)flat, (unsigned)(flat + half), o0, o1);
        bits = o0;
    } else {
        threefry42((unsigned)(flat - half), (unsigned)flat, o0, o1);
        bits = o1;
    }
    unsigned fb = (bits >> 9) | 0x3F800000u;
    float f = __uint_as_float(fb) - 1.0f;        // [0, 1)
    const float tiny = 1.17549435e-38f;
    float u = fmaxf(tiny, f * (1.0f - tiny) + tiny);
    double lu = log((double)u);
    return (float)(-log(-lu));
}

__global__ void __launch_bounds__(THREADS)
rd_kernel(const float* __restrict__ logits,
          const void* __restrict__ x_t_raw,
          float* __restrict__ out) {            // __output__ dtype = float32
    const int tid = threadIdx.x;
    const int row = blockIdx.x * RPC + tid;

    // ---- Fused dtype-probe + token load: one 4-byte load per thread; the
    // warp's own 32 values decide the encoding via ballots. 8-byte loads are
    // issued only after the ballot proves the buffer is 8 bytes/element
    // (odd- or even-word-zero pattern; false positive p ~ 50257^-16).
    unsigned w32 = ((const unsigned*)x_t_raw)[row];
    float fv = __uint_as_float(w32);
    bool okf32 = (fv >= 0.0f && fv < 50257.0f && fv == floorf(fv));
    unsigned ball_f32  = __ballot_sync(0xFFFFFFFFu, okf32);
    unsigned ball_zero = __ballot_sync(0xFFFFFFFFu, w32 == 0u);

    int tok;
    if (ball_f32 == 0xFFFFFFFFu) {
        tok = (int)fv;                                   // float32 tokens
    } else if ((ball_zero & 0xAAAAAAAAu) == 0xAAAAAAAAu ||
               (ball_zero & 0x55555555u) == 0x55555555u) {
        // 8-byte elements: odd words all zero (int64) or low mantissa words
        // all zero (float64 integral tokens). Safe to load 8 bytes now.
        unsigned long long w64 = ((const unsigned long long*)x_t_raw)[row];
        if ((w64 >> 32) == 0ull && (unsigned)w64 < 50257u)
            tok = (int)(long long)w64;                   // int64 (or f64 zero)
        else
            tok = (int)__longlong_as_double((long long)w64);  // float64
    } else {
        tok = (int)w32;                                  // int32 tokens
    }

    const bool masked = (tok == MASK_ID);
    if (!masked) out[row] = (float)tok;       // tokens < 2^24: exact in f32

    // Single fused barrier + block-wide masked count (no shared atomic,
    // no init race on the fast path).
    const int M = __syncthreads_count(masked);
    if (M == 0) return;                       // common case: done

    // ---- Rare path: collect masked rows (needs its own barrier pair) ----
    __shared__ int maskedRows[RPC];
    __shared__ int nMasked;
    if (tid == 0) nMasked = 0;
    __syncthreads();
    if (masked) {
        int idx = atomicAdd(&nMasked, 1);
        maskedRows[idx] = row;
    }
    __syncthreads();

    // ---------------- masked rows: full top-k / top-p / gumbel pipeline ----
    __shared__ unsigned hist[4096];
    __shared__ unsigned coarse[THREADS];
    __shared__ float    candV[NCAND];
    __shared__ int      candI[NCAND];
    __shared__ unsigned candCount;
    __shared__ unsigned sh_binB, sh_subB, sh_countAbove, sh_refine;
    __shared__ unsigned long long redK[THREADS];
    __shared__ int      redS[THREADS];
    __shared__ float    topV[TOPK];
    __shared__ int      topI[TOPK];
    __shared__ float    scores[TOPK];
    __shared__ int      sh_keptK;

    const float NEGINF = __uint_as_float(0xFF800000u);

    for (int m = 0; m < M; m++) {
        const int mrow = maskedRows[m];
        const float* rowp = logits + (long long)mrow * VOCAB;

        // Pass 1: 12-bit histogram of order keys
        for (int i = tid; i < 4096; i += THREADS) hist[i] = 0u;
        __syncthreads();
        for (int v = tid; v < VOCAB; v += THREADS) {
            atomicAdd(&hist[ordkey(rowp[v]) >> 20], 1u);
        }
        __syncthreads();

        // Find bin containing the 50th largest (scan from top)
        {
            unsigned s = 0;
            #pragma unroll
            for (int j = 0; j < 16; j++) s += hist[tid * 16 + j];
            coarse[tid] = s;
        }
        __syncthreads();
        if (tid == 0) {
            unsigned cum = 0;
            int cb = 255;
            for (; cb > 0; cb--) {
                if (cum + coarse[cb] >= TOPK) break;
                cum += coarse[cb];
            }
            int bin = cb * 16 + 15;
            for (;; bin--) {
                if (cum + hist[bin] >= TOPK) break;
                cum += hist[bin];
            }
            sh_binB = (unsigned)bin;
            sh_countAbove = cum;
            sh_refine = (cum + hist[bin] > NCAND) ? 1u : 0u;
            candCount = 0u;
        }
        __syncthreads();
        const unsigned bB = sh_binB;

        if (sh_refine) {
            // Refine with next 12 key bits (only within boundary bin)
            for (int i = tid; i < 4096; i += THREADS) hist[i] = 0u;
            __syncthreads();
            for (int v = tid; v < VOCAB; v += THREADS) {
                unsigned k = ordkey(rowp[v]);
                if ((k >> 20) == bB) atomicAdd(&hist[(k >> 8) & 0xFFFu], 1u);
            }
            __syncthreads();
            {
                unsigned s = 0;
                #pragma unroll
                for (int j = 0; j < 16; j++) s += hist[tid * 16 + j];
                coarse[tid] = s;
            }
            __syncthreads();
            if (tid == 0) {
                unsigned cum = sh_countAbove;
                int cb = 255;
                for (; cb > 0; cb--) {
                    if (cum + coarse[cb] >= TOPK) break;
                    cum += coarse[cb];
                }
                int bin = cb * 16 + 15;
                for (;; bin--) {
                    if (cum + hist[bin] >= TOPK) break;
                    cum += hist[bin];
                }
                sh_subB = (unsigned)bin;
            }
            __syncthreads();
            const unsigned sB = sh_subB;
            for (int v = tid; v < VOCAB; v += THREADS) {
                unsigned k = ordkey(rowp[v]);
                unsigned t12 = k >> 20;
                if (t12 > bB || (t12 == bB && ((k >> 8) & 0xFFFu) >= sB)) {
                    unsigned pos = atomicAdd(&candCount, 1u);
                    if (pos < NCAND) { candV[pos] = rowp[v]; candI[pos] = v; }
                }
            }
        } else {
            // Pass 2: collect candidates (key bin >= boundary bin); row is L2-hot
            for (int v = tid; v < VOCAB; v += THREADS) {
                if ((ordkey(rowp[v]) >> 20) >= bB) {
                    unsigned pos = atomicAdd(&candCount, 1u);
                    if (pos < NCAND) { candV[pos] = rowp[v]; candI[pos] = v; }
                }
            }
        }
        __syncthreads();
        const int C = (int)min(candCount, (unsigned)NCAND);

        // Extract top-50 sorted desc (ties: ascending vocab index) via 50 block argmaxes.
        for (int it = 0; it < TOPK; it++) {
            unsigned long long bk = 0ull; int bs = 0;
            for (int c = tid; c < C; c += THREADS) {
                unsigned long long k =
                    ((unsigned long long)ordkey(candV[c]) << 32) |
                    (unsigned long long)(0xFFFFFFFFu - (unsigned)candI[c]);
                if (k > bk) { bk = k; bs = c; }
            }
            redK[tid] = bk; redS[tid] = bs;
            __syncthreads();
            for (int off = THREADS / 2; off > 0; off >>= 1) {
                if (tid < off && redK[tid + off] > redK[tid]) {
                    redK[tid] = redK[tid + off];
                    redS[tid] = redS[tid + off];
                }
                __syncthreads();
            }
            if (tid == 0) {
                int slot = redS[0];
                topV[it] = candV[slot];
                topI[it] = candI[slot];
                candV[slot] = NEGINF;    // mark taken
            }
            __syncthreads();
        }

        // Softmax over the 50 finite entries, sequential cumsum,
        // nucleus prefix: keep i>=1 iff cum_{i-1} <= 0.9.
        if (tid == 0) {
            float mx = topV[0];
            float p[TOPK];
            float sum = 0.0f;
            for (int i = 0; i < TOPK; i++) { p[i] = expf(topV[i] - mx); sum += p[i]; }
            float cum = p[0] / sum;
            int K = 1;
            while (K < TOPK && cum <= TOPP) { cum += p[K] / sum; K++; }
            sh_keptK = K;
        }
        __syncthreads();
        const int K = sh_keptK;

        // Gumbel scores for kept tokens (one lane per kept slot)
        if (tid < K) {
            long long flat = (long long)mrow * VOCAB + (long long)topI[tid];
            scores[tid] = topV[tid] + gumbel_at(flat);
        }
        __syncthreads();

        // argmax over kept set; tie-break = smallest vocab index (JAX argmax)
        if (tid == 0) {
            float best = scores[0];
            int bestIdx = topI[0];
            for (int i = 1; i < K; i++) {
                float s = scores[i];
                int idx = topI[i];
                if (s > best || (s == best && idx < bestIdx)) { best = s; bestIdx = idx; }
            }
            out[mrow] = (float)bestIdx;
        }
        __syncthreads();   // protect shared reuse for next masked row
    }
}

extern "C" void kernel_launch(void* const* d_in, const int* in_sizes, int n_in,
                              void* d_out, int out_size) {
    // x_t = smallest input, logits = largest (robust to ordering / extra inputs).
    int li = 0, si = 0;
    for (int i = 1; i < n_in; i++) {
        if (in_sizes[i] > in_sizes[li]) li = i;
        if (in_sizes[i] < in_sizes[si]) si = i;
    }
    const float* logits = (const float*)d_in[li];
    const void*  x_t    = d_in[si];
    rd_kernel<<<GRID, THREADS>>>(logits, x_t, (float*)d_out);
}